// round 9
// baseline (speedup 1.0000x reference)
#include <cuda_runtime.h>
#include <cuda_bf16.h>
#include <math.h>
#include <stdint.h>
#include <stddef.h>

#define Bsz 8
#define Tsz 1024
#define Vsz 256
#define Dsz 4096
#define Ksz 8192
#define Hsz 512
#define Msz (Bsz*Tsz)
#define CH  (3*Hsz)

// ===========================================================================
// PTX helpers (baseline PTX only)
// ===========================================================================
__device__ __forceinline__ uint32_t smem_to_u32(const void* p) {
    uint32_t a;
    asm("{ .reg .u64 t; cvta.to.shared.u64 t, %1; cvt.u32.u64 %0, t; }" : "=r"(a) : "l"(p));
    return a;
}
__device__ __forceinline__ void cp16(uint32_t s, const void* g) {
    asm volatile("cp.async.cg.shared.global [%0], [%1], 16;" :: "r"(s), "l"(g));
}
#define CP_COMMIT() asm volatile("cp.async.commit_group;" ::: "memory")

__device__ __forceinline__ void ldmx4(uint32_t* r, uint32_t addr) {
    asm volatile("ldmatrix.sync.aligned.m8n8.x4.shared.b16 {%0,%1,%2,%3}, [%4];"
        : "=r"(r[0]), "=r"(r[1]), "=r"(r[2]), "=r"(r[3]) : "r"(addr));
}

__device__ __forceinline__ void mma16816(float& d0, float& d1, float& d2, float& d3,
                                         uint32_t a0, uint32_t a1, uint32_t a2, uint32_t a3,
                                         uint32_t b0, uint32_t b1) {
    asm volatile(
        "mma.sync.aligned.m16n8k16.row.col.f32.bf16.bf16.f32 "
        "{%0,%1,%2,%3},{%4,%5,%6,%7},{%8,%9},{%0,%1,%2,%3};"
        : "+f"(d0), "+f"(d1), "+f"(d2), "+f"(d3)
        : "r"(a0), "r"(a1), "r"(a2), "r"(a3), "r"(b0), "r"(b1));
}

// ===========================================================================
// Scratch
// ===========================================================================
#define ALN __align__(256)
__device__ ALN __nv_bfloat16 g_tri[(size_t)Msz*Dsz];
__device__ ALN __nv_bfloat16 g_cb16[(size_t)Vsz*Dsz];
__device__ ALN __nv_bfloat16 g_khi[(size_t)Ksz*Dsz];
__device__ ALN __nv_bfloat16 g_Pb[(size_t)Msz*Ksz];      // P -> scores -> attn (in place)
__device__ ALN __nv_bfloat16 g_cbkb[(size_t)Vsz*Ksz];
__device__ ALN float g_hdcf[(size_t)Msz*Hsz];
__device__ ALN float g_cpw[(size_t)Vsz*Hsz];
__device__ ALN __nv_bfloat16 g_vthi[(size_t)Hsz*Ksz];
__device__ ALN float g_ret[(size_t)Msz*Hsz];
__device__ ALN __nv_bfloat16 g_pwthi[(size_t)Hsz*Dsz];
__device__ ALN __nv_bfloat16 g_pwtlo[(size_t)Hsz*Dsz];
__device__ ALN __nv_bfloat16 g_xhi[(size_t)Msz*CH];
__device__ ALN __nv_bfloat16 g_xlo[(size_t)Msz*CH];
__device__ ALN __nv_bfloat16 g_w1thi[(size_t)Hsz*CH];
__device__ ALN __nv_bfloat16 g_w1tlo[(size_t)Hsz*CH];
__device__ ALN __nv_bfloat16 g_w2thi[(size_t)Hsz*Hsz];
__device__ ALN __nv_bfloat16 g_w2tlo[(size_t)Hsz*Hsz];
__device__ ALN __nv_bfloat16 g_w3thi[(size_t)Hsz*Hsz];
__device__ ALN __nv_bfloat16 g_w3tlo[(size_t)Hsz*Hsz];
__device__ ALN __nv_bfloat16 g_hwthi[(size_t)Vsz*Hsz];
__device__ ALN __nv_bfloat16 g_hwtlo[(size_t)Vsz*Hsz];
__device__ ALN __nv_bfloat16 g_h1hi[(size_t)Msz*Hsz];
__device__ ALN __nv_bfloat16 g_h1lo[(size_t)Msz*Hsz];
__device__ ALN __nv_bfloat16 g_h2hi[(size_t)Msz*Hsz];
__device__ ALN __nv_bfloat16 g_h2lo[(size_t)Msz*Hsz];
__device__ ALN __nv_bfloat16 g_h3hi[(size_t)Msz*Hsz];
__device__ ALN __nv_bfloat16 g_h3lo[(size_t)Msz*Hsz];

__device__ __forceinline__ void split_write(float v, __nv_bfloat16* hi,
                                            __nv_bfloat16* lo, size_t o) {
    __nv_bfloat16 h = __float2bfloat16(v);
    hi[o] = h;
    lo[o] = __float2bfloat16(v - __bfloat162float(h));
}

// ===========================================================================
// WIDE 1-pass GEMM: C[M,N] = epi( A@B^T ), NT, bf16 operands.
// BM=128, BN=256, 256 threads (2x4 warps, 64x64 warp tile -> MMA-bound).
// EPI 3: bf16 = v*alpha;  EPI 0: fp32 = v*alpha.
// ===========================================================================
#define WATILE (128*80)
#define WBTILE (256*80)
#define WSTAGE (WATILE + WBTILE)   // 30720
#define SMEMW  (4 * WSTAGE)        // 122880

template<int EPI>
__global__ void __launch_bounds__(256)
gemm_wide(const __nv_bfloat16* __restrict__ A, const __nv_bfloat16* __restrict__ B,
          float alpha, float* __restrict__ C, __nv_bfloat16* __restrict__ Cb,
          int M, int N, int Kd, int grid_m, int grid_n)
{
    extern __shared__ __align__(128) char smem[];
    const uint32_t sb = smem_to_u32(smem);
    const int tid = threadIdx.x;

    // rasterization (GROUP_M=8)
    const int pid   = blockIdx.x;
    const int width = 8 * grid_n;
    const int group = pid / width;
    const int rem   = pid % width;
    int gm = grid_m - group * 8; if (gm > 8) gm = 8;
    const int m0 = (group * 8 + rem % gm) * 128;
    const int n0 = (rem / gm) * 256;

    const int nch = Kd / 32;

    auto issue = [&](int c, int stg) {
        const uint32_t base = sb + (uint32_t)stg * WSTAGE;
        const int k0 = c * 32;
        #pragma unroll
        for (int i = 0; i < 2; ++i) {
            const int id = i * 256 + tid;
            const int r  = id >> 2;
            const int cc = id & 3;
            cp16(base + (uint32_t)r * 80 + cc * 16,
                 A + (size_t)(m0 + r) * Kd + k0 + cc * 8);
        }
        #pragma unroll
        for (int i = 0; i < 4; ++i) {
            const int id = i * 256 + tid;
            const int r  = id >> 2;
            const int cc = id & 3;
            cp16(base + WATILE + (uint32_t)r * 80 + cc * 16,
                 B + (size_t)(n0 + r) * Kd + k0 + cc * 8);
        }
        CP_COMMIT();
    };

    issue(0, 0);
    issue(1, 1);

    const int wid  = tid >> 5;
    const int lane = tid & 31;
    const int wm = (wid & 1) * 64;    // 2 m-groups
    const int wn = (wid >> 1) * 64;   // 4 n-groups
    const int lr = lane & 15;
    const int lc = lane >> 4;

    float acc[4][8][4];
    #pragma unroll
    for (int i = 0; i < 4; ++i)
        #pragma unroll
        for (int j = 0; j < 8; ++j)
            #pragma unroll
            for (int e = 0; e < 4; ++e) acc[i][j][e] = 0.0f;

    for (int c = 0; c < nch; ++c) {
        if (c + 2 < nch) {
            issue(c + 2, (c + 2) & 3);
            asm volatile("cp.async.wait_group 2;" ::: "memory");
        } else if (c + 1 < nch) {
            asm volatile("cp.async.wait_group 1;" ::: "memory");
        } else {
            asm volatile("cp.async.wait_group 0;" ::: "memory");
        }
        __syncthreads();

        const uint32_t stb = sb + (uint32_t)(c & 3) * WSTAGE;
        #pragma unroll
        for (int ks = 0; ks < 2; ++ks) {
            const uint32_t coff = (uint32_t)(ks * 16 + lc * 8) * 2;
            uint32_t bh[8][2];
            #pragma unroll
            for (int gq = 0; gq < 4; ++gq) {
                uint32_t t4[4];
                ldmx4(t4, stb + WATILE + (uint32_t)(wn + gq * 16 + lr) * 80 + coff);
                bh[2*gq][0] = t4[0]; bh[2*gq+1][0] = t4[1];
                bh[2*gq][1] = t4[2]; bh[2*gq+1][1] = t4[3];
            }
            uint32_t ah[4][4];
            #pragma unroll
            for (int mt = 0; mt < 4; ++mt)
                ldmx4(ah[mt], stb + (uint32_t)(wm + mt * 16 + lr) * 80 + coff);
            #pragma unroll
            for (int mt = 0; mt < 4; ++mt)
                #pragma unroll
                for (int nt = 0; nt < 8; ++nt) {
                    float* d = acc[mt][nt];
                    mma16816(d[0], d[1], d[2], d[3],
                             ah[mt][0], ah[mt][1], ah[mt][2], ah[mt][3],
                             bh[nt][0], bh[nt][1]);
                }
        }
    }

    const int gid = lane >> 2;
    const int tig = lane & 3;
    #pragma unroll
    for (int mt = 0; mt < 4; ++mt) {
        #pragma unroll
        for (int half = 0; half < 2; ++half) {
            const int m = m0 + wm + mt * 16 + gid + half * 8;
            #pragma unroll
            for (int nt = 0; nt < 8; ++nt) {
                const int n = n0 + wn + nt * 8 + tig * 2;
                const float v0 = acc[mt][nt][half * 2 + 0] * alpha;
                const float v1 = acc[mt][nt][half * 2 + 1] * alpha;
                if (EPI == 0) {
                    float2 o; o.x = v0; o.y = v1;
                    *(float2*)&C[(size_t)m * N + n] = o;
                } else {
                    __nv_bfloat162 hh;
                    hh.x = __float2bfloat16(v0);
                    hh.y = __float2bfloat16(v1);
                    *(__nv_bfloat162*)&Cb[(size_t)m * N + n] = hh;
                }
            }
        }
    }
}

// ===========================================================================
// Multi-pass GEMM (Round 8, unchanged): BM=BN=128, split passes.
//  Passes: (Ahi,Bhi) always; (Ahi,Blo) if BPARTS==2; (Alo,Bhi) if APARTS==2.
//  EPI 0: fp32 = v*alpha;  1: bf16 hi/lo = gelu(v+bias);  2: fp32 = v+bias
// ===========================================================================
#define TILEB (128*80)

template<int APARTS, int BPARTS, int EPI>
__global__ void __launch_bounds__(256)
gemm_mma(const __nv_bfloat16* __restrict__ Ahi, const __nv_bfloat16* __restrict__ Alo,
         const __nv_bfloat16* __restrict__ Bhi, const __nv_bfloat16* __restrict__ Blo,
         const float* __restrict__ bias, float alpha,
         float* __restrict__ C, __nv_bfloat16* __restrict__ Chi,
         __nv_bfloat16* __restrict__ Clo,
         int M, int N, int Kd, int grid_m, int grid_n)
{
    constexpr int PARTS = APARTS + BPARTS;
    constexpr uint32_t STAGE = PARTS * TILEB;
    extern __shared__ __align__(128) char smem[];
    const uint32_t sb = smem_to_u32(smem);
    const int tid = threadIdx.x;

    const int pid   = blockIdx.x;
    const int width = 8 * grid_n;
    const int group = pid / width;
    const int rem   = pid % width;
    int gm = grid_m - group * 8; if (gm > 8) gm = 8;
    const int m0 = (group * 8 + rem % gm) * 128;
    const int n0 = (rem / gm) * 128;

    const int nch = Kd / 32;

    auto issue = [&](int c, int stg) {
        const uint32_t base = sb + (uint32_t)stg * STAGE;
        const int k0 = c * 32;
        #pragma unroll
        for (int i = 0; i < 2; ++i) {
            const int id = i * 256 + tid;
            const int r  = id >> 2;
            const int cc = id & 3;
            const uint32_t so = (uint32_t)r * 80 + cc * 16;
            const size_t  go = (size_t)k0 + cc * 8;
            cp16(base + so, Ahi + (size_t)(m0 + r) * Kd + go);
            if (APARTS == 2)
                cp16(base + TILEB + so, Alo + (size_t)(m0 + r) * Kd + go);
            cp16(base + APARTS * TILEB + so, Bhi + (size_t)(n0 + r) * Kd + go);
            if (BPARTS == 2)
                cp16(base + (APARTS + 1) * TILEB + so, Blo + (size_t)(n0 + r) * Kd + go);
        }
        CP_COMMIT();
    };

    issue(0, 0);
    issue(1, 1);

    const int wid  = tid >> 5;
    const int lane = tid & 31;
    const int wm = (wid & 3) * 32;
    const int wn = (wid >> 2) * 64;
    const int lr = lane & 15;
    const int lc = lane >> 4;

    float acc[2][8][4];
    #pragma unroll
    for (int i = 0; i < 2; ++i)
        #pragma unroll
        for (int j = 0; j < 8; ++j)
            #pragma unroll
            for (int e = 0; e < 4; ++e) acc[i][j][e] = 0.0f;

    for (int c = 0; c < nch; ++c) {
        if (c + 2 < nch) {
            issue(c + 2, (c + 2) & 3);
            asm volatile("cp.async.wait_group 2;" ::: "memory");
        } else if (c + 1 < nch) {
            asm volatile("cp.async.wait_group 1;" ::: "memory");
        } else {
            asm volatile("cp.async.wait_group 0;" ::: "memory");
        }
        __syncthreads();

        const uint32_t stb = sb + (uint32_t)(c & 3) * STAGE;
        #pragma unroll
        for (int ks = 0; ks < 2; ++ks) {
            const uint32_t coff = (uint32_t)(ks * 16 + lc * 8) * 2;
            uint32_t bh[8][2], bl[8][2];
            #pragma unroll
            for (int gq = 0; gq < 4; ++gq) {
                uint32_t t4[4];
                const uint32_t addr = stb + APARTS * TILEB
                                    + (uint32_t)(wn + gq * 16 + lr) * 80 + coff;
                ldmx4(t4, addr);
                bh[2*gq][0] = t4[0]; bh[2*gq+1][0] = t4[1];
                bh[2*gq][1] = t4[2]; bh[2*gq+1][1] = t4[3];
                if (BPARTS == 2) {
                    ldmx4(t4, addr + TILEB);
                    bl[2*gq][0] = t4[0]; bl[2*gq+1][0] = t4[1];
                    bl[2*gq][1] = t4[2]; bl[2*gq+1][1] = t4[3];
                }
            }
            uint32_t ah[2][4], al[2][4];
            #pragma unroll
            for (int mt = 0; mt < 2; ++mt) {
                const uint32_t addr = stb + (uint32_t)(wm + mt * 16 + lr) * 80 + coff;
                ldmx4(ah[mt], addr);
                if (APARTS == 2) ldmx4(al[mt], addr + TILEB);
            }
            #pragma unroll
            for (int mt = 0; mt < 2; ++mt)
                #pragma unroll
                for (int nt = 0; nt < 8; ++nt) {
                    float* d = acc[mt][nt];
                    mma16816(d[0], d[1], d[2], d[3],
                             ah[mt][0], ah[mt][1], ah[mt][2], ah[mt][3],
                             bh[nt][0], bh[nt][1]);
                    if (BPARTS == 2)
                        mma16816(d[0], d[1], d[2], d[3],
                                 ah[mt][0], ah[mt][1], ah[mt][2], ah[mt][3],
                                 bl[nt][0], bl[nt][1]);
                    if (APARTS == 2)
                        mma16816(d[0], d[1], d[2], d[3],
                                 al[mt][0], al[mt][1], al[mt][2], al[mt][3],
                                 bh[nt][0], bh[nt][1]);
                }
        }
    }

    const int gid = lane >> 2;
    const int tig = lane & 3;
    #pragma unroll
    for (int mt = 0; mt < 2; ++mt) {
        #pragma unroll
        for (int half = 0; half < 2; ++half) {
            const int m = m0 + wm + mt * 16 + gid + half * 8;
            #pragma unroll
            for (int nt = 0; nt < 8; ++nt) {
                const int n = n0 + wn + nt * 8 + tig * 2;
                float v0 = acc[mt][nt][half * 2 + 0];
                float v1 = acc[mt][nt][half * 2 + 1];
                if (EPI == 0) {
                    float2 o; o.x = v0 * alpha; o.y = v1 * alpha;
                    *(float2*)&C[(size_t)m * N + n] = o;
                } else if (EPI == 2) {
                    float2 o; o.x = v0 + bias[n]; o.y = v1 + bias[n + 1];
                    *(float2*)&C[(size_t)m * N + n] = o;
                } else {
                    v0 += bias[n];
                    v1 += bias[n + 1];
                    v0 = 0.5f * v0 * (1.0f + erff(v0 * 0.70710678118654752f));
                    v1 = 0.5f * v1 * (1.0f + erff(v1 * 0.70710678118654752f));
                    __nv_bfloat16 h0 = __float2bfloat16(v0);
                    __nv_bfloat16 h1 = __float2bfloat16(v1);
                    __nv_bfloat162 hh; hh.x = h0; hh.y = h1;
                    __nv_bfloat162 ll;
                    ll.x = __float2bfloat16(v0 - __bfloat162float(h0));
                    ll.y = __float2bfloat16(v1 - __bfloat162float(h1));
                    *(__nv_bfloat162*)&Chi[(size_t)m * N + n] = hh;
                    *(__nv_bfloat162*)&Clo[(size_t)m * N + n] = ll;
                }
            }
        }
    }
}

// ===========================================================================
// Elementwise kernels
// ===========================================================================
__global__ void cvt_bf16(const float* __restrict__ in, __nv_bfloat16* __restrict__ out) {
    size_t i = (size_t)blockIdx.x * 256 + threadIdx.x;
    out[i] = __float2bfloat16(in[i]);
}

// fp32 [R,C] -> bf16 [C,R] (hi only)
__global__ void cvt_T(const float* __restrict__ in, __nv_bfloat16* __restrict__ hi,
                      int R, int C) {
    __shared__ float tile[32][33];
    const int c0 = blockIdx.x * 32, r0 = blockIdx.y * 32;
    const int x = threadIdx.x, y = threadIdx.y;
    #pragma unroll
    for (int j = y; j < 32; j += 8)
        tile[j][x] = in[(size_t)(r0 + j) * C + (c0 + x)];
    __syncthreads();
    #pragma unroll
    for (int j = y; j < 32; j += 8)
        hi[(size_t)(c0 + j) * R + (r0 + x)] = __float2bfloat16(tile[x][j]);
}

// fp32 [R,C] -> hi/lo bf16 [C,R]
__global__ void split_T(const float* __restrict__ in, __nv_bfloat16* __restrict__ hi,
                        __nv_bfloat16* __restrict__ lo, int R, int C) {
    __shared__ float tile[32][33];
    const int c0 = blockIdx.x * 32, r0 = blockIdx.y * 32;
    const int x = threadIdx.x, y = threadIdx.y;
    #pragma unroll
    for (int j = y; j < 32; j += 8)
        tile[j][x] = in[(size_t)(r0 + j) * C + (c0 + x)];
    __syncthreads();
    #pragma unroll
    for (int j = y; j < 32; j += 8)
        split_write(tile[x][j], hi, lo, (size_t)(c0 + j) * R + (r0 + x));
}

// trigram: tri[m,d] = cb[i0][d]*cb[i1][(d-1)%D]*cb[i2][(d-2)%D], 0 for t<2
__global__ void tri_kernel(const int* __restrict__ idx, const float* __restrict__ cb,
                           __nv_bfloat16* __restrict__ tri) {
    const int m = blockIdx.y;
    const int t = m & (Tsz - 1);
    const int d = blockIdx.x * 256 + threadIdx.x;
    float v = 0.0f;
    if (t >= 2) {
        const int i0 = idx[m], i1 = idx[m-1], i2 = idx[m-2];
        const int dm1 = (d + Dsz - 1) & (Dsz - 1);
        const int dm2 = (d + Dsz - 2) & (Dsz - 1);
        v = cb[(size_t)i0 * Dsz + d] * cb[(size_t)i1 * Dsz + dm1] * cb[(size_t)i2 * Dsz + dm2];
    }
    tri[(size_t)m * Dsz + d] = __float2bfloat16(v);
}

// decay scan over t (bf16 in/out): S = decay(0.7*P + 0.3*cbk[idx]) * norm(t) * D^-0.5
__global__ void scan_scores_b(__nv_bfloat16* __restrict__ P,
                              const __nv_bfloat16* __restrict__ cbk,
                              const int* __restrict__ idx) {
    const int b = blockIdx.y;
    const int k = blockIdx.x * 256 + threadIdx.x;
    __shared__ int sidx[Tsz];
    for (int i = threadIdx.x; i < Tsz; i += 256) sidx[i] = idx[b * Tsz + i];
    __syncthreads();
    float acc = 0.0f, p = 1.0f;
    const size_t base = (size_t)b * Tsz * Ksz + k;
    #pragma unroll 4
    for (int t = 0; t < Tsz; ++t) {
        const float h = 0.7f * __bfloat162float(P[base + (size_t)t * Ksz])
                      + 0.3f * __bfloat162float(cbk[(size_t)sidx[t] * Ksz + k]);
        acc = 0.95f * acc + h;
        p *= 0.95f;
        P[base + (size_t)t * Ksz] =
            __float2bfloat16(acc * (0.05f / (1.0f - p)) * 0.015625f);
    }
}

// decay scan on hdcf: hdcf = decay(0.7*tpw + 0.3*cpw[idx]) * norm + proj_b
__global__ void scan_hdcf(float* __restrict__ tpw, const float* __restrict__ cpw,
                          const int* __restrict__ idx, const float* __restrict__ pb) {
    const int b = blockIdx.y;
    const int h = blockIdx.x * 128 + threadIdx.x;
    __shared__ int sidx[Tsz];
    for (int i = threadIdx.x; i < Tsz; i += 128) sidx[i] = idx[b * Tsz + i];
    __syncthreads();
    float acc = 0.0f, p = 1.0f;
    const float bias = pb[h];
    const size_t base = (size_t)b * Tsz * Hsz + h;
    #pragma unroll 4
    for (int t = 0; t < Tsz; ++t) {
        const float v = 0.7f * tpw[base + (size_t)t * Hsz]
                      + 0.3f * cpw[(size_t)sidx[t] * Hsz + h];
        acc = 0.95f * acc + v;
        p *= 0.95f;
        tpw[base + (size_t)t * Hsz] = acc * (0.05f / (1.0f - p)) + bias;
    }
}

__device__ __forceinline__ float blk_rmax(float v, float* red) {
    #pragma unroll
    for (int o = 16; o; o >>= 1) v = fmaxf(v, __shfl_xor_sync(0xffffffffu, v, o));
    const int tid = threadIdx.x;
    if ((tid & 31) == 0) red[tid >> 5] = v;
    __syncthreads();
    if (tid == 0) { float w = red[0]; for (int i = 1; i < 8; ++i) w = fmaxf(w, red[i]); red[0] = w; }
    __syncthreads();
    const float r = red[0]; __syncthreads(); return r;
}
__device__ __forceinline__ float blk_rsum(float v, float* red) {
    #pragma unroll
    for (int o = 16; o; o >>= 1) v += __shfl_xor_sync(0xffffffffu, v, o);
    const int tid = threadIdx.x;
    if ((tid & 31) == 0) red[tid >> 5] = v;
    __syncthreads();
    if (tid == 0) { float w = red[0]; for (int i = 1; i < 8; ++i) w += red[i]; red[0] = w; }
    __syncthreads();
    const float r = red[0]; __syncthreads(); return r;
}

// row softmax over K=8192, bf16 in-place
__global__ void softmax_b(__nv_bfloat16* __restrict__ S) {
    __shared__ float red[8];
    const int m = blockIdx.x;
    const int tid = threadIdx.x;
    __nv_bfloat16* row = S + (size_t)m * Ksz;
    float v[32];
    float lm = -1e30f;
    #pragma unroll
    for (int i = 0; i < 32; ++i) {
        v[i] = __bfloat162float(row[tid + i * 256]);
        lm = fmaxf(lm, v[i]);
    }
    const float rmax = blk_rmax(lm, red);
    float ls = 0.0f;
    #pragma unroll
    for (int i = 0; i < 32; ++i) { v[i] = expf(v[i] - rmax); ls += v[i]; }
    const float inv = 1.0f / blk_rsum(ls, red);
    #pragma unroll
    for (int i = 0; i < 32; ++i)
        row[tid + i * 256] = __float2bfloat16(v[i] * inv);
}

// concat [hdcf | ret | res+pos] + LayerNorm -> bf16 hi/lo
__global__ void concat_ln(const float* __restrict__ hdcf, const float* __restrict__ ret,
                          const int* __restrict__ idx, const float* __restrict__ res_embed,
                          const float* __restrict__ pos_embed, const float* __restrict__ gamma,
                          const float* __restrict__ beta, __nv_bfloat16* __restrict__ xhi,
                          __nv_bfloat16* __restrict__ xlo) {
    __shared__ float red[8];
    const int m = blockIdx.x;
    const int t = m & (Tsz - 1);
    const int iv = idx[m];
    const int tid = threadIdx.x;
    float v[6];
    #pragma unroll
    for (int j = 0; j < 6; ++j) {
        const int col = tid + j * 256;
        float val;
        if (col < Hsz)            val = hdcf[(size_t)m * Hsz + col];
        else if (col < 2 * Hsz)   val = ret[(size_t)m * Hsz + (col - Hsz)];
        else                      val = res_embed[(size_t)iv * Hsz + (col - 2 * Hsz)]
                                      + pos_embed[(size_t)t  * Hsz + (col - 2 * Hsz)];
        v[j] = val;
    }
    float s = 0.0f, s2 = 0.0f;
    #pragma unroll
    for (int j = 0; j < 6; ++j) { s += v[j]; s2 += v[j] * v[j]; }
    const float mean = blk_rsum(s, red) * (1.0f / CH);
    const float var  = blk_rsum(s2, red) * (1.0f / CH) - mean * mean;
    const float rstd = rsqrtf(var + 1e-5f);
    #pragma unroll
    for (int j = 0; j < 6; ++j) {
        const int col = tid + j * 256;
        split_write((v[j] - mean) * rstd * gamma[col] + beta[col], xhi, xlo,
                    (size_t)m * CH + col);
    }
}

// ===========================================================================
// Launch
// ===========================================================================
#define SMEM12 (4 * 3 * TILEB)   // 122880
#define SMEM22 (4 * 4 * TILEB)   // 163840

extern "C" void kernel_launch(void* const* d_in, const int* in_sizes, int n_in,
                              void* d_out, int out_size)
{
    const int*   idx       = (const int*)  d_in[0];
    const float* codebook  = (const float*)d_in[1];
    const float* mem_keys  = (const float*)d_in[2];
    const float* mem_vals  = (const float*)d_in[3];
    const float* proj_w    = (const float*)d_in[4];
    const float* proj_b    = (const float*)d_in[5];
    const float* res_embed = (const float*)d_in[6];
    const float* pos_embed = (const float*)d_in[7];
    const float* ln_g      = (const float*)d_in[8];
    const float* ln_b      = (const float*)d_in[9];
    const float* w1        = (const float*)d_in[10];
    const float* b1        = (const float*)d_in[11];
    const float* w2        = (const float*)d_in[12];
    const float* b2        = (const float*)d_in[13];
    const float* w3        = (const float*)d_in[14];
    const float* b3        = (const float*)d_in[15];
    const float* head_w    = (const float*)d_in[16];
    const float* head_b    = (const float*)d_in[17];
    float* out = (float*)d_out;

    static bool attr_done = false;
    if (!attr_done) {
        cudaFuncSetAttribute(gemm_wide<3>,    cudaFuncAttributeMaxDynamicSharedMemorySize, SMEMW);
        cudaFuncSetAttribute(gemm_wide<0>,    cudaFuncAttributeMaxDynamicSharedMemorySize, SMEMW);
        cudaFuncSetAttribute(gemm_mma<1,2,0>, cudaFuncAttributeMaxDynamicSharedMemorySize, SMEM12);
        cudaFuncSetAttribute(gemm_mma<2,2,1>, cudaFuncAttributeMaxDynamicSharedMemorySize, SMEM22);
        cudaFuncSetAttribute(gemm_mma<2,2,2>, cudaFuncAttributeMaxDynamicSharedMemorySize, SMEM22);
        attr_done = true;
    }

    __nv_bfloat16 *tri, *cb16, *khi, *Pb, *cbkb, *vthi, *pwthi, *pwtlo;
    __nv_bfloat16 *xhi, *xlo, *w1thi, *w1tlo, *w2thi, *w2tlo, *w3thi, *w3tlo, *hwthi, *hwtlo;
    __nv_bfloat16 *h1hi, *h1lo, *h2hi, *h2lo, *h3hi, *h3lo;
    float *hdcf, *cpw, *ret;
    cudaGetSymbolAddress((void**)&tri,   g_tri);
    cudaGetSymbolAddress((void**)&cb16,  g_cb16);
    cudaGetSymbolAddress((void**)&khi,   g_khi);
    cudaGetSymbolAddress((void**)&Pb,    g_Pb);
    cudaGetSymbolAddress((void**)&cbkb,  g_cbkb);
    cudaGetSymbolAddress((void**)&hdcf,  g_hdcf);
    cudaGetSymbolAddress((void**)&cpw,   g_cpw);
    cudaGetSymbolAddress((void**)&vthi,  g_vthi);
    cudaGetSymbolAddress((void**)&ret,   g_ret);
    cudaGetSymbolAddress((void**)&pwthi, g_pwthi);
    cudaGetSymbolAddress((void**)&pwtlo, g_pwtlo);
    cudaGetSymbolAddress((void**)&xhi,   g_xhi);
    cudaGetSymbolAddress((void**)&xlo,   g_xlo);
    cudaGetSymbolAddress((void**)&w1thi, g_w1thi);
    cudaGetSymbolAddress((void**)&w1tlo, g_w1tlo);
    cudaGetSymbolAddress((void**)&w2thi, g_w2thi);
    cudaGetSymbolAddress((void**)&w2tlo, g_w2tlo);
    cudaGetSymbolAddress((void**)&w3thi, g_w3thi);
    cudaGetSymbolAddress((void**)&w3tlo, g_w3tlo);
    cudaGetSymbolAddress((void**)&hwthi, g_hwthi);
    cudaGetSymbolAddress((void**)&hwtlo, g_hwtlo);
    cudaGetSymbolAddress((void**)&h1hi,  g_h1hi);
    cudaGetSymbolAddress((void**)&h1lo,  g_h1lo);
    cudaGetSymbolAddress((void**)&h2hi,  g_h2hi);
    cudaGetSymbolAddress((void**)&h2lo,  g_h2lo);
    cudaGetSymbolAddress((void**)&h3hi,  g_h3hi);
    cudaGetSymbolAddress((void**)&h3lo,  g_h3lo);

    // ---- operand prep ----
    cvt_bf16<<<(Vsz*Dsz)/256, 256>>>(codebook, cb16);
    tri_kernel<<<dim3(Dsz/256, Msz), 256>>>(idx, codebook, tri);
    cvt_bf16<<<(int)(((size_t)Ksz*Dsz)/256), 256>>>(mem_keys, khi);
    cvt_T<<<dim3(Hsz/32, Ksz/32), dim3(32,8)>>>(mem_vals, vthi, Ksz, Hsz);
    split_T<<<dim3(Hsz/32, Dsz/32), dim3(32,8)>>>(proj_w, pwthi, pwtlo, Dsz, Hsz);
    split_T<<<dim3(Hsz/32, CH/32),  dim3(32,8)>>>(w1,     w1thi, w1tlo, CH,  Hsz);
    split_T<<<dim3(Hsz/32, Hsz/32), dim3(32,8)>>>(w2,     w2thi, w2tlo, Hsz, Hsz);
    split_T<<<dim3(Hsz/32, Hsz/32), dim3(32,8)>>>(w3,     w3thi, w3tlo, Hsz, Hsz);
    split_T<<<dim3(Vsz/32, Hsz/32), dim3(32,8)>>>(head_w, hwthi, hwtlo, Hsz, Vsz);

    // ---- GEMMs + scans ----
    // P = tri @ keys^T  [8192, 8192] — 1 pass, wide kernel, bf16 out
    gemm_wide<3><<<(Msz/128)*(Ksz/256), 256, SMEMW>>>(
        tri, khi, 1.0f, nullptr, Pb, Msz, Ksz, Dsz, Msz/128, Ksz/256);
    // cbk = cb @ keys^T  [256, 8192] — 1 pass, wide, bf16 out
    gemm_wide<3><<<(Vsz/128)*(Ksz/256), 256, SMEMW>>>(
        cb16, khi, 1.0f, nullptr, cbkb, Vsz, Ksz, Dsz, Vsz/128, Ksz/256);
    // tpw = tri @ proj_w^T [8192, 512] — 2 passes, fp32 out
    gemm_mma<1,2,0><<<(Msz/128)*(Hsz/128), 256, SMEM12>>>(
        tri, nullptr, pwthi, pwtlo, nullptr, 1.0f, hdcf, nullptr, nullptr,
        Msz, Hsz, Dsz, Msz/128, Hsz/128);
    // cpw = cb @ proj_w^T [256, 512] — 2 passes
    gemm_mma<1,2,0><<<(Vsz/128)*(Hsz/128), 256, SMEM12>>>(
        cb16, nullptr, pwthi, pwtlo, nullptr, 1.0f, cpw, nullptr, nullptr,
        Vsz, Hsz, Dsz, Vsz/128, Hsz/128);

    scan_scores_b<<<dim3(Ksz/256, Bsz), 256>>>(Pb, cbkb, idx);
    softmax_b<<<Msz, 256>>>(Pb);
    scan_hdcf<<<dim3(Hsz/128, Bsz), 128>>>(hdcf, cpw, idx, proj_b);

    // ret = attn @ vals^T [8192, 512] — 1 pass, wide, fp32 out
    gemm_wide<0><<<(Msz/128)*(Hsz/256), 256, SMEMW>>>(
        Pb, vthi, 1.0f, ret, nullptr, Msz, Hsz, Ksz, Msz/128, Hsz/256);

    concat_ln<<<Msz, 256>>>(hdcf, ret, idx, res_embed, pos_embed, ln_g, ln_b, xhi, xlo);

    // MLP — 3 passes each (error budget requires it)
    gemm_mma<2,2,1><<<(Msz/128)*(Hsz/128), 256, SMEM22>>>(
        xhi, xlo, w1thi, w1tlo, b1, 1.0f, nullptr, h1hi, h1lo,
        Msz, Hsz, CH, Msz/128, Hsz/128);
    gemm_mma<2,2,1><<<(Msz/128)*(Hsz/128), 256, SMEM22>>>(
        h1hi, h1lo, w2thi, w2tlo, b2, 1.0f, nullptr, h2hi, h2lo,
        Msz, Hsz, Hsz, Msz/128, Hsz/128);
    gemm_mma<2,2,1><<<(Msz/128)*(Hsz/128), 256, SMEM22>>>(
        h2hi, h2lo, w3thi, w3tlo, b3, 1.0f, nullptr, h3hi, h3lo,
        Msz, Hsz, Hsz, Msz/128, Hsz/128);
    // logits — 3 passes (h3lo term is 0.2% of logits; keep — Round 7 lesson)
    gemm_mma<2,2,2><<<(Msz/128)*(Vsz/128), 256, SMEM22>>>(
        h3hi, h3lo, hwthi, hwtlo, head_b, 1.0f, out, nullptr, nullptr,
        Msz, Vsz, Hsz, Msz/128, Vsz/128);
}

// round 10
// speedup vs baseline: 1.1454x; 1.1454x over previous
#include <cuda_runtime.h>
#include <cuda_bf16.h>
#include <math.h>
#include <stdint.h>
#include <stddef.h>

#define Bsz 8
#define Tsz 1024
#define Vsz 256
#define Dsz 4096
#define Ksz 8192
#define Hsz 512
#define Msz (Bsz*Tsz)
#define CH  (3*Hsz)

// ===========================================================================
// PTX helpers (baseline PTX only)
// ===========================================================================
__device__ __forceinline__ uint32_t smem_to_u32(const void* p) {
    uint32_t a;
    asm("{ .reg .u64 t; cvta.to.shared.u64 t, %1; cvt.u32.u64 %0, t; }" : "=r"(a) : "l"(p));
    return a;
}
__device__ __forceinline__ void cp16(uint32_t s, const void* g) {
    asm volatile("cp.async.cg.shared.global [%0], [%1], 16;" :: "r"(s), "l"(g));
}
#define CP_COMMIT() asm volatile("cp.async.commit_group;" ::: "memory")

__device__ __forceinline__ void ldmx4(uint32_t* r, uint32_t addr) {
    asm volatile("ldmatrix.sync.aligned.m8n8.x4.shared.b16 {%0,%1,%2,%3}, [%4];"
        : "=r"(r[0]), "=r"(r[1]), "=r"(r[2]), "=r"(r[3]) : "r"(addr));
}

__device__ __forceinline__ void mma16816(float& d0, float& d1, float& d2, float& d3,
                                         uint32_t a0, uint32_t a1, uint32_t a2, uint32_t a3,
                                         uint32_t b0, uint32_t b1) {
    asm volatile(
        "mma.sync.aligned.m16n8k16.row.col.f32.bf16.bf16.f32 "
        "{%0,%1,%2,%3},{%4,%5,%6,%7},{%8,%9},{%0,%1,%2,%3};"
        : "+f"(d0), "+f"(d1), "+f"(d2), "+f"(d3)
        : "r"(a0), "r"(a1), "r"(a2), "r"(a3), "r"(b0), "r"(b1));
}

// ===========================================================================
// Scratch
// ===========================================================================
#define ALN __align__(256)
__device__ ALN __nv_bfloat16 g_tri[(size_t)Msz*Dsz];
__device__ ALN __nv_bfloat16 g_cb16[(size_t)Vsz*Dsz];
__device__ ALN __nv_bfloat16 g_khi[(size_t)Ksz*Dsz];
__device__ ALN __nv_bfloat16 g_Pb[(size_t)Msz*Ksz];      // P -> scores -> attn (in place)
__device__ ALN __nv_bfloat16 g_cbkb[(size_t)Vsz*Ksz];
__device__ ALN float g_hdcf[(size_t)Msz*Hsz];
__device__ ALN float g_cpw[(size_t)Vsz*Hsz];
__device__ ALN __nv_bfloat16 g_vthi[(size_t)Hsz*Ksz];
__device__ ALN float g_ret[(size_t)Msz*Hsz];
__device__ ALN __nv_bfloat16 g_pwthi[(size_t)Hsz*Dsz];
__device__ ALN __nv_bfloat16 g_pwtlo[(size_t)Hsz*Dsz];
__device__ ALN __nv_bfloat16 g_xhi[(size_t)Msz*CH];
__device__ ALN __nv_bfloat16 g_xlo[(size_t)Msz*CH];
__device__ ALN __nv_bfloat16 g_w1thi[(size_t)Hsz*CH];
__device__ ALN __nv_bfloat16 g_w1tlo[(size_t)Hsz*CH];
__device__ ALN __nv_bfloat16 g_w2thi[(size_t)Hsz*Hsz];
__device__ ALN __nv_bfloat16 g_w2tlo[(size_t)Hsz*Hsz];
__device__ ALN __nv_bfloat16 g_w3thi[(size_t)Hsz*Hsz];
__device__ ALN __nv_bfloat16 g_w3tlo[(size_t)Hsz*Hsz];
__device__ ALN __nv_bfloat16 g_hwthi[(size_t)Vsz*Hsz];
__device__ ALN __nv_bfloat16 g_hwtlo[(size_t)Vsz*Hsz];
__device__ ALN __nv_bfloat16 g_h1hi[(size_t)Msz*Hsz];
__device__ ALN __nv_bfloat16 g_h1lo[(size_t)Msz*Hsz];
__device__ ALN __nv_bfloat16 g_h2hi[(size_t)Msz*Hsz];
__device__ ALN __nv_bfloat16 g_h2lo[(size_t)Msz*Hsz];
__device__ ALN __nv_bfloat16 g_h3hi[(size_t)Msz*Hsz];
__device__ ALN __nv_bfloat16 g_h3lo[(size_t)Msz*Hsz];

__device__ __forceinline__ void split_write(float v, __nv_bfloat16* hi,
                                            __nv_bfloat16* lo, size_t o) {
    __nv_bfloat16 h = __float2bfloat16(v);
    hi[o] = h;
    lo[o] = __float2bfloat16(v - __bfloat162float(h));
}

// ===========================================================================
// mma.sync GEMM: C[M,N] = epi( sum over split passes of A@B^T ), NT, bf16.
//  Passes: (Ahi,Bhi) always; (Ahi,Blo) if BPARTS==2; (Alo,Bhi) if APARTS==2.
//  EPI 0: fp32 = v*alpha;   1: bf16 hi/lo = gelu(v+bias);
//  EPI 2: fp32 = v+bias;    3: bf16 = v*alpha (hi only)
//  MINB: min CTAs/SM (2 for 1-pass variants: caps regs at 128, spill-free)
// BM=BN=128, BK=32, 256 threads, 4-stage cp.async. Rows padded to 80 B.
// ===========================================================================
#define TILEB (128*80)

template<int APARTS, int BPARTS, int EPI, int MINB>
__global__ void __launch_bounds__(256, MINB)
gemm_mma(const __nv_bfloat16* __restrict__ Ahi, const __nv_bfloat16* __restrict__ Alo,
         const __nv_bfloat16* __restrict__ Bhi, const __nv_bfloat16* __restrict__ Blo,
         const float* __restrict__ bias, float alpha,
         float* __restrict__ C, __nv_bfloat16* __restrict__ Chi,
         __nv_bfloat16* __restrict__ Clo,
         int M, int N, int Kd, int grid_m, int grid_n)
{
    constexpr int PARTS = APARTS + BPARTS;
    constexpr uint32_t STAGE = PARTS * TILEB;
    extern __shared__ __align__(128) char smem[];
    const uint32_t sb = smem_to_u32(smem);
    const int tid = threadIdx.x;

    // tile rasterization (GROUP_M=8 for L2 reuse)
    const int pid   = blockIdx.x;
    const int width = 8 * grid_n;
    const int group = pid / width;
    const int rem   = pid % width;
    int gm = grid_m - group * 8; if (gm > 8) gm = 8;
    const int m0 = (group * 8 + rem % gm) * 128;
    const int n0 = (rem / gm) * 128;

    const int nch = Kd / 32;

    auto issue = [&](int c, int stg) {
        const uint32_t base = sb + (uint32_t)stg * STAGE;
        const int k0 = c * 32;
        #pragma unroll
        for (int i = 0; i < 2; ++i) {
            const int id = i * 256 + tid;
            const int r  = id >> 2;
            const int cc = id & 3;
            const uint32_t so = (uint32_t)r * 80 + cc * 16;
            const size_t  go = (size_t)k0 + cc * 8;
            cp16(base + so, Ahi + (size_t)(m0 + r) * Kd + go);
            if (APARTS == 2)
                cp16(base + TILEB + so, Alo + (size_t)(m0 + r) * Kd + go);
            cp16(base + APARTS * TILEB + so, Bhi + (size_t)(n0 + r) * Kd + go);
            if (BPARTS == 2)
                cp16(base + (APARTS + 1) * TILEB + so, Blo + (size_t)(n0 + r) * Kd + go);
        }
        CP_COMMIT();
    };

    issue(0, 0);
    issue(1, 1);

    const int wid  = tid >> 5;
    const int lane = tid & 31;
    const int wm = (wid & 3) * 32;
    const int wn = (wid >> 2) * 64;
    const int lr = lane & 15;
    const int lc = lane >> 4;

    float acc[2][8][4];
    #pragma unroll
    for (int i = 0; i < 2; ++i)
        #pragma unroll
        for (int j = 0; j < 8; ++j)
            #pragma unroll
            for (int e = 0; e < 4; ++e) acc[i][j][e] = 0.0f;

    for (int c = 0; c < nch; ++c) {
        if (c + 2 < nch) {
            issue(c + 2, (c + 2) & 3);
            asm volatile("cp.async.wait_group 2;" ::: "memory");
        } else if (c + 1 < nch) {
            asm volatile("cp.async.wait_group 1;" ::: "memory");
        } else {
            asm volatile("cp.async.wait_group 0;" ::: "memory");
        }
        __syncthreads();

        const uint32_t stb = sb + (uint32_t)(c & 3) * STAGE;
        #pragma unroll
        for (int ks = 0; ks < 2; ++ks) {
            const uint32_t coff = (uint32_t)(ks * 16 + lc * 8) * 2;
            uint32_t bh[8][2], bl[8][2];
            #pragma unroll
            for (int gq = 0; gq < 4; ++gq) {
                uint32_t t4[4];
                const uint32_t addr = stb + APARTS * TILEB
                                    + (uint32_t)(wn + gq * 16 + lr) * 80 + coff;
                ldmx4(t4, addr);
                bh[2*gq][0] = t4[0]; bh[2*gq+1][0] = t4[1];
                bh[2*gq][1] = t4[2]; bh[2*gq+1][1] = t4[3];
                if (BPARTS == 2) {
                    ldmx4(t4, addr + TILEB);
                    bl[2*gq][0] = t4[0]; bl[2*gq+1][0] = t4[1];
                    bl[2*gq][1] = t4[2]; bl[2*gq+1][1] = t4[3];
                }
            }
            uint32_t ah[2][4], al[2][4];
            #pragma unroll
            for (int mt = 0; mt < 2; ++mt) {
                const uint32_t addr = stb + (uint32_t)(wm + mt * 16 + lr) * 80 + coff;
                ldmx4(ah[mt], addr);
                if (APARTS == 2) ldmx4(al[mt], addr + TILEB);
            }
            #pragma unroll
            for (int mt = 0; mt < 2; ++mt)
                #pragma unroll
                for (int nt = 0; nt < 8; ++nt) {
                    float* d = acc[mt][nt];
                    mma16816(d[0], d[1], d[2], d[3],
                             ah[mt][0], ah[mt][1], ah[mt][2], ah[mt][3],
                             bh[nt][0], bh[nt][1]);
                    if (BPARTS == 2)
                        mma16816(d[0], d[1], d[2], d[3],
                                 ah[mt][0], ah[mt][1], ah[mt][2], ah[mt][3],
                                 bl[nt][0], bl[nt][1]);
                    if (APARTS == 2)
                        mma16816(d[0], d[1], d[2], d[3],
                                 al[mt][0], al[mt][1], al[mt][2], al[mt][3],
                                 bh[nt][0], bh[nt][1]);
                }
        }
    }

    const int gid = lane >> 2;
    const int tig = lane & 3;
    #pragma unroll
    for (int mt = 0; mt < 2; ++mt) {
        #pragma unroll
        for (int half = 0; half < 2; ++half) {
            const int m = m0 + wm + mt * 16 + gid + half * 8;
            #pragma unroll
            for (int nt = 0; nt < 8; ++nt) {
                const int n = n0 + wn + nt * 8 + tig * 2;
                float v0 = acc[mt][nt][half * 2 + 0];
                float v1 = acc[mt][nt][half * 2 + 1];
                if (EPI == 0) {
                    float2 o; o.x = v0 * alpha; o.y = v1 * alpha;
                    *(float2*)&C[(size_t)m * N + n] = o;
                } else if (EPI == 2) {
                    float2 o; o.x = v0 + bias[n]; o.y = v1 + bias[n + 1];
                    *(float2*)&C[(size_t)m * N + n] = o;
                } else if (EPI == 3) {
                    __nv_bfloat162 hh;
                    hh.x = __float2bfloat16(v0 * alpha);
                    hh.y = __float2bfloat16(v1 * alpha);
                    *(__nv_bfloat162*)&Chi[(size_t)m * N + n] = hh;
                } else {
                    v0 += bias[n];
                    v1 += bias[n + 1];
                    v0 = 0.5f * v0 * (1.0f + erff(v0 * 0.70710678118654752f));
                    v1 = 0.5f * v1 * (1.0f + erff(v1 * 0.70710678118654752f));
                    __nv_bfloat16 h0 = __float2bfloat16(v0);
                    __nv_bfloat16 h1 = __float2bfloat16(v1);
                    __nv_bfloat162 hh; hh.x = h0; hh.y = h1;
                    __nv_bfloat162 ll;
                    ll.x = __float2bfloat16(v0 - __bfloat162float(h0));
                    ll.y = __float2bfloat16(v1 - __bfloat162float(h1));
                    *(__nv_bfloat162*)&Chi[(size_t)m * N + n] = hh;
                    *(__nv_bfloat162*)&Clo[(size_t)m * N + n] = ll;
                }
            }
        }
    }
}

// ===========================================================================
// Elementwise kernels
// ===========================================================================
__global__ void cvt_bf16(const float* __restrict__ in, __nv_bfloat16* __restrict__ out) {
    size_t i = (size_t)blockIdx.x * 256 + threadIdx.x;
    out[i] = __float2bfloat16(in[i]);
}

// fp32 [R,C] -> bf16 [C,R] (hi only)
__global__ void cvt_T(const float* __restrict__ in, __nv_bfloat16* __restrict__ hi,
                      int R, int C) {
    __shared__ float tile[32][33];
    const int c0 = blockIdx.x * 32, r0 = blockIdx.y * 32;
    const int x = threadIdx.x, y = threadIdx.y;
    #pragma unroll
    for (int j = y; j < 32; j += 8)
        tile[j][x] = in[(size_t)(r0 + j) * C + (c0 + x)];
    __syncthreads();
    #pragma unroll
    for (int j = y; j < 32; j += 8)
        hi[(size_t)(c0 + j) * R + (r0 + x)] = __float2bfloat16(tile[x][j]);
}

// fp32 [R,C] -> hi/lo bf16 [C,R]
__global__ void split_T(const float* __restrict__ in, __nv_bfloat16* __restrict__ hi,
                        __nv_bfloat16* __restrict__ lo, int R, int C) {
    __shared__ float tile[32][33];
    const int c0 = blockIdx.x * 32, r0 = blockIdx.y * 32;
    const int x = threadIdx.x, y = threadIdx.y;
    #pragma unroll
    for (int j = y; j < 32; j += 8)
        tile[j][x] = in[(size_t)(r0 + j) * C + (c0 + x)];
    __syncthreads();
    #pragma unroll
    for (int j = y; j < 32; j += 8)
        split_write(tile[x][j], hi, lo, (size_t)(c0 + j) * R + (r0 + x));
}

// trigram from bf16 codebook (exact ±1 products):
// tri[m,d] = cb[i0][d]*cb[i1][(d-1)%D]*cb[i2][(d-2)%D], 0 for t<2
__global__ void tri_kernel(const int* __restrict__ idx,
                           const __nv_bfloat16* __restrict__ cb,
                           __nv_bfloat16* __restrict__ tri) {
    const int m = blockIdx.y;
    const int t = m & (Tsz - 1);
    const int d = blockIdx.x * 256 + threadIdx.x;
    float v = 0.0f;
    if (t >= 2) {
        const int i0 = idx[m], i1 = idx[m-1], i2 = idx[m-2];
        const int dm1 = (d + Dsz - 1) & (Dsz - 1);
        const int dm2 = (d + Dsz - 2) & (Dsz - 1);
        v = __bfloat162float(cb[(size_t)i0 * Dsz + d])
          * __bfloat162float(cb[(size_t)i1 * Dsz + dm1])
          * __bfloat162float(cb[(size_t)i2 * Dsz + dm2]);
    }
    tri[(size_t)m * Dsz + d] = __float2bfloat16(v);
}

// decay scan over t (bf16 in/out): S = decay(0.7*P + 0.3*cbk[idx]) * norm(t) * D^-0.5
__global__ void scan_scores_b(__nv_bfloat16* __restrict__ P,
                              const __nv_bfloat16* __restrict__ cbk,
                              const int* __restrict__ idx) {
    const int b = blockIdx.y;
    const int k = blockIdx.x * 256 + threadIdx.x;
    __shared__ int sidx[Tsz];
    for (int i = threadIdx.x; i < Tsz; i += 256) sidx[i] = idx[b * Tsz + i];
    __syncthreads();
    float acc = 0.0f, p = 1.0f;
    const size_t base = (size_t)b * Tsz * Ksz + k;
    #pragma unroll 4
    for (int t = 0; t < Tsz; ++t) {
        const float h = 0.7f * __bfloat162float(P[base + (size_t)t * Ksz])
                      + 0.3f * __bfloat162float(cbk[(size_t)sidx[t] * Ksz + k]);
        acc = 0.95f * acc + h;
        p *= 0.95f;
        P[base + (size_t)t * Ksz] =
            __float2bfloat16(acc * (0.05f / (1.0f - p)) * 0.015625f);
    }
}

// decay scan on hdcf: hdcf = decay(0.7*tpw + 0.3*cpw[idx]) * norm + proj_b
__global__ void scan_hdcf(float* __restrict__ tpw, const float* __restrict__ cpw,
                          const int* __restrict__ idx, const float* __restrict__ pb) {
    const int b = blockIdx.y;
    const int h = blockIdx.x * 128 + threadIdx.x;
    __shared__ int sidx[Tsz];
    for (int i = threadIdx.x; i < Tsz; i += 128) sidx[i] = idx[b * Tsz + i];
    __syncthreads();
    float acc = 0.0f, p = 1.0f;
    const float bias = pb[h];
    const size_t base = (size_t)b * Tsz * Hsz + h;
    #pragma unroll 4
    for (int t = 0; t < Tsz; ++t) {
        const float v = 0.7f * tpw[base + (size_t)t * Hsz]
                      + 0.3f * cpw[(size_t)sidx[t] * Hsz + h];
        acc = 0.95f * acc + v;
        p *= 0.95f;
        tpw[base + (size_t)t * Hsz] = acc * (0.05f / (1.0f - p)) + bias;
    }
}

__device__ __forceinline__ float blk_rmax(float v, float* red) {
    #pragma unroll
    for (int o = 16; o; o >>= 1) v = fmaxf(v, __shfl_xor_sync(0xffffffffu, v, o));
    const int tid = threadIdx.x;
    if ((tid & 31) == 0) red[tid >> 5] = v;
    __syncthreads();
    if (tid == 0) { float w = red[0]; for (int i = 1; i < 8; ++i) w = fmaxf(w, red[i]); red[0] = w; }
    __syncthreads();
    const float r = red[0]; __syncthreads(); return r;
}
__device__ __forceinline__ float blk_rsum(float v, float* red) {
    #pragma unroll
    for (int o = 16; o; o >>= 1) v += __shfl_xor_sync(0xffffffffu, v, o);
    const int tid = threadIdx.x;
    if ((tid & 31) == 0) red[tid >> 5] = v;
    __syncthreads();
    if (tid == 0) { float w = red[0]; for (int i = 1; i < 8; ++i) w += red[i]; red[0] = w; }
    __syncthreads();
    const float r = red[0]; __syncthreads(); return r;
}

// row softmax over K=8192, bf16 in-place
__global__ void softmax_b(__nv_bfloat16* __restrict__ S) {
    __shared__ float red[8];
    const int m = blockIdx.x;
    const int tid = threadIdx.x;
    __nv_bfloat16* row = S + (size_t)m * Ksz;
    float v[32];
    float lm = -1e30f;
    #pragma unroll
    for (int i = 0; i < 32; ++i) {
        v[i] = __bfloat162float(row[tid + i * 256]);
        lm = fmaxf(lm, v[i]);
    }
    const float rmax = blk_rmax(lm, red);
    float ls = 0.0f;
    #pragma unroll
    for (int i = 0; i < 32; ++i) { v[i] = expf(v[i] - rmax); ls += v[i]; }
    const float inv = 1.0f / blk_rsum(ls, red);
    #pragma unroll
    for (int i = 0; i < 32; ++i)
        row[tid + i * 256] = __float2bfloat16(v[i] * inv);
}

// concat [hdcf | ret | res+pos] + LayerNorm -> bf16 hi/lo
__global__ void concat_ln(const float* __restrict__ hdcf, const float* __restrict__ ret,
                          const int* __restrict__ idx, const float* __restrict__ res_embed,
                          const float* __restrict__ pos_embed, const float* __restrict__ gamma,
                          const float* __restrict__ beta, __nv_bfloat16* __restrict__ xhi,
                          __nv_bfloat16* __restrict__ xlo) {
    __shared__ float red[8];
    const int m = blockIdx.x;
    const int t = m & (Tsz - 1);
    const int iv = idx[m];
    const int tid = threadIdx.x;
    float v[6];
    #pragma unroll
    for (int j = 0; j < 6; ++j) {
        const int col = tid + j * 256;
        float val;
        if (col < Hsz)            val = hdcf[(size_t)m * Hsz + col];
        else if (col < 2 * Hsz)   val = ret[(size_t)m * Hsz + (col - Hsz)];
        else                      val = res_embed[(size_t)iv * Hsz + (col - 2 * Hsz)]
                                      + pos_embed[(size_t)t  * Hsz + (col - 2 * Hsz)];
        v[j] = val;
    }
    float s = 0.0f, s2 = 0.0f;
    #pragma unroll
    for (int j = 0; j < 6; ++j) { s += v[j]; s2 += v[j] * v[j]; }
    const float mean = blk_rsum(s, red) * (1.0f / CH);
    const float var  = blk_rsum(s2, red) * (1.0f / CH) - mean * mean;
    const float rstd = rsqrtf(var + 1e-5f);
    #pragma unroll
    for (int j = 0; j < 6; ++j) {
        const int col = tid + j * 256;
        split_write((v[j] - mean) * rstd * gamma[col] + beta[col], xhi, xlo,
                    (size_t)m * CH + col);
    }
}

// ===========================================================================
// Launch
// ===========================================================================
#define SMEM11 (4 * 2 * TILEB)   // 81920 — 1-pass, 2 CTAs/SM
#define SMEM12 (4 * 3 * TILEB)   // 122880
#define SMEM22 (4 * 4 * TILEB)   // 163840

extern "C" void kernel_launch(void* const* d_in, const int* in_sizes, int n_in,
                              void* d_out, int out_size)
{
    const int*   idx       = (const int*)  d_in[0];
    const float* codebook  = (const float*)d_in[1];
    const float* mem_keys  = (const float*)d_in[2];
    const float* mem_vals  = (const float*)d_in[3];
    const float* proj_w    = (const float*)d_in[4];
    const float* proj_b    = (const float*)d_in[5];
    const float* res_embed = (const float*)d_in[6];
    const float* pos_embed = (const float*)d_in[7];
    const float* ln_g      = (const float*)d_in[8];
    const float* ln_b      = (const float*)d_in[9];
    const float* w1        = (const float*)d_in[10];
    const float* b1        = (const float*)d_in[11];
    const float* w2        = (const float*)d_in[12];
    const float* b2        = (const float*)d_in[13];
    const float* w3        = (const float*)d_in[14];
    const float* b3        = (const float*)d_in[15];
    const float* head_w    = (const float*)d_in[16];
    const float* head_b    = (const float*)d_in[17];
    float* out = (float*)d_out;

    static bool attr_done = false;
    if (!attr_done) {
        cudaFuncSetAttribute(gemm_mma<1,1,3,2>, cudaFuncAttributeMaxDynamicSharedMemorySize, SMEM11);
        cudaFuncSetAttribute(gemm_mma<1,1,0,2>, cudaFuncAttributeMaxDynamicSharedMemorySize, SMEM11);
        cudaFuncSetAttribute(gemm_mma<1,2,0,1>, cudaFuncAttributeMaxDynamicSharedMemorySize, SMEM12);
        cudaFuncSetAttribute(gemm_mma<2,2,1,1>, cudaFuncAttributeMaxDynamicSharedMemorySize, SMEM22);
        cudaFuncSetAttribute(gemm_mma<2,2,2,1>, cudaFuncAttributeMaxDynamicSharedMemorySize, SMEM22);
        attr_done = true;
    }

    __nv_bfloat16 *tri, *cb16, *khi, *Pb, *cbkb, *vthi, *pwthi, *pwtlo;
    __nv_bfloat16 *xhi, *xlo, *w1thi, *w1tlo, *w2thi, *w2tlo, *w3thi, *w3tlo, *hwthi, *hwtlo;
    __nv_bfloat16 *h1hi, *h1lo, *h2hi, *h2lo, *h3hi, *h3lo;
    float *hdcf, *cpw, *ret;
    cudaGetSymbolAddress((void**)&tri,   g_tri);
    cudaGetSymbolAddress((void**)&cb16,  g_cb16);
    cudaGetSymbolAddress((void**)&khi,   g_khi);
    cudaGetSymbolAddress((void**)&Pb,    g_Pb);
    cudaGetSymbolAddress((void**)&cbkb,  g_cbkb);
    cudaGetSymbolAddress((void**)&hdcf,  g_hdcf);
    cudaGetSymbolAddress((void**)&cpw,   g_cpw);
    cudaGetSymbolAddress((void**)&vthi,  g_vthi);
    cudaGetSymbolAddress((void**)&ret,   g_ret);
    cudaGetSymbolAddress((void**)&pwthi, g_pwthi);
    cudaGetSymbolAddress((void**)&pwtlo, g_pwtlo);
    cudaGetSymbolAddress((void**)&xhi,   g_xhi);
    cudaGetSymbolAddress((void**)&xlo,   g_xlo);
    cudaGetSymbolAddress((void**)&w1thi, g_w1thi);
    cudaGetSymbolAddress((void**)&w1tlo, g_w1tlo);
    cudaGetSymbolAddress((void**)&w2thi, g_w2thi);
    cudaGetSymbolAddress((void**)&w2tlo, g_w2tlo);
    cudaGetSymbolAddress((void**)&w3thi, g_w3thi);
    cudaGetSymbolAddress((void**)&w3tlo, g_w3tlo);
    cudaGetSymbolAddress((void**)&hwthi, g_hwthi);
    cudaGetSymbolAddress((void**)&hwtlo, g_hwtlo);
    cudaGetSymbolAddress((void**)&h1hi,  g_h1hi);
    cudaGetSymbolAddress((void**)&h1lo,  g_h1lo);
    cudaGetSymbolAddress((void**)&h2hi,  g_h2hi);
    cudaGetSymbolAddress((void**)&h2lo,  g_h2lo);
    cudaGetSymbolAddress((void**)&h3hi,  g_h3hi);
    cudaGetSymbolAddress((void**)&h3lo,  g_h3lo);

    // ---- operand prep ----
    cvt_bf16<<<(Vsz*Dsz)/256, 256>>>(codebook, cb16);
    tri_kernel<<<dim3(Dsz/256, Msz), 256>>>(idx, cb16, tri);
    cvt_bf16<<<(int)(((size_t)Ksz*Dsz)/256), 256>>>(mem_keys, khi);
    cvt_T<<<dim3(Hsz/32, Ksz/32), dim3(32,8)>>>(mem_vals, vthi, Ksz, Hsz);
    split_T<<<dim3(Hsz/32, Dsz/32), dim3(32,8)>>>(proj_w, pwthi, pwtlo, Dsz, Hsz);
    split_T<<<dim3(Hsz/32, CH/32),  dim3(32,8)>>>(w1,     w1thi, w1tlo, CH,  Hsz);
    split_T<<<dim3(Hsz/32, Hsz/32), dim3(32,8)>>>(w2,     w2thi, w2tlo, Hsz, Hsz);
    split_T<<<dim3(Hsz/32, Hsz/32), dim3(32,8)>>>(w3,     w3thi, w3tlo, Hsz, Hsz);
    split_T<<<dim3(Vsz/32, Hsz/32), dim3(32,8)>>>(head_w, hwthi, hwtlo, Hsz, Vsz);

    // ---- GEMMs + scans ----
    // P = tri @ keys^T  [8192, 8192] — 1 pass, 2 CTAs/SM, bf16 out
    gemm_mma<1,1,3,2><<<(Msz/128)*(Ksz/128), 256, SMEM11>>>(
        tri, nullptr, khi, nullptr, nullptr, 1.0f, nullptr, Pb, nullptr,
        Msz, Ksz, Dsz, Msz/128, Ksz/128);
    // cbk = cb @ keys^T  [256, 8192] — 1 pass, bf16 out
    gemm_mma<1,1,3,2><<<(Vsz/128)*(Ksz/128), 256, SMEM11>>>(
        cb16, nullptr, khi, nullptr, nullptr, 1.0f, nullptr, cbkb, nullptr,
        Vsz, Ksz, Dsz, Vsz/128, Ksz/128);
    // tpw = tri @ proj_w^T [8192, 512] — 2 passes, fp32 out
    gemm_mma<1,2,0,1><<<(Msz/128)*(Hsz/128), 256, SMEM12>>>(
        tri, nullptr, pwthi, pwtlo, nullptr, 1.0f, hdcf, nullptr, nullptr,
        Msz, Hsz, Dsz, Msz/128, Hsz/128);
    // cpw = cb @ proj_w^T [256, 512] — 2 passes
    gemm_mma<1,2,0,1><<<(Vsz/128)*(Hsz/128), 256, SMEM12>>>(
        cb16, nullptr, pwthi, pwtlo, nullptr, 1.0f, cpw, nullptr, nullptr,
        Vsz, Hsz, Dsz, Vsz/128, Hsz/128);

    scan_scores_b<<<dim3(Ksz/256, Bsz), 256>>>(Pb, cbkb, idx);
    softmax_b<<<Msz, 256>>>(Pb);
    scan_hdcf<<<dim3(Hsz/128, Bsz), 128>>>(hdcf, cpw, idx, proj_b);

    // ret = attn @ vals^T [8192, 512] — 1 pass, 2 CTAs/SM, fp32 out
    gemm_mma<1,1,0,2><<<(Msz/128)*(Hsz/128), 256, SMEM11>>>(
        Pb, nullptr, vthi, nullptr, nullptr, 1.0f, ret, nullptr, nullptr,
        Msz, Hsz, Ksz, Msz/128, Hsz/128);

    concat_ln<<<Msz, 256>>>(hdcf, ret, idx, res_embed, pos_embed, ln_g, ln_b, xhi, xlo);

    // MLP — 3 passes each (error budget requires it)
    gemm_mma<2,2,1,1><<<(Msz/128)*(Hsz/128), 256, SMEM22>>>(
        xhi, xlo, w1thi, w1tlo, b1, 1.0f, nullptr, h1hi, h1lo,
        Msz, Hsz, CH, Msz/128, Hsz/128);
    gemm_mma<2,2,1,1><<<(Msz/128)*(Hsz/128), 256, SMEM22>>>(
        h1hi, h1lo, w2thi, w2tlo, b2, 1.0f, nullptr, h2hi, h2lo,
        Msz, Hsz, Hsz, Msz/128, Hsz/128);
    gemm_mma<2,2,1,1><<<(Msz/128)*(Hsz/128), 256, SMEM22>>>(
        h2hi, h2lo, w3thi, w3tlo, b3, 1.0f, nullptr, h3hi, h3lo,
        Msz, Hsz, Hsz, Msz/128, Hsz/128);
    // logits — 3 passes (h3lo term is 0.2% of logits; keep — Round 7 lesson)
    gemm_mma<2,2,2,1><<<(Msz/128)*(Vsz/128), 256, SMEM22>>>(
        h3hi, h3lo, hwthi, hwtlo, head_b, 1.0f, out, nullptr, nullptr,
        Msz, Vsz, Hsz, Msz/128, Vsz/128);
}